// round 2
// baseline (speedup 1.0000x reference)
#include <cuda_runtime.h>
#include <cstdint>

// AWD-LSTM, persistent-kernel version. T=1024, B=64, DIN=512, H=1024.
// Inputs: x[T,B,DIN], h0[B,H], c0[B,H], Wi[4H,DIN], bi[4H], Wh[4H,H], bh[4H],
//         input_tokens[T,B] i32.  Output: [ out(T*B*H) | hT(B*H) | cT(B*H) ].

#define TT 1024
#define BB 64
#define DD 512
#define HH 1024
#define GG 4096
#define GRID 128
#define BSTR 1028               // Bs row stride in 4B words
#define BH   (BB * HH)
#define TBH  ((size_t)TT * BB * HH)

__device__ float    g_xi[(size_t)TT * BB * GG];   // 1.07 GB scratch
__device__ unsigned g_h[2][BB * HH];              // tf32 h (keep-folded), double-buffered
__device__ int      g_arrive[GRID];

__device__ __forceinline__ unsigned f2tf32(float f) {
    unsigned r;
    asm("cvt.rna.tf32.f32 %0, %1;" : "=r"(r) : "f"(f));
    return r;
}

__device__ __forceinline__ uint2 ldcg_u2(const unsigned* p) {
    unsigned long long v = __ldcg((const unsigned long long*)p);
    uint2 r; r.x = (unsigned)v; r.y = (unsigned)(v >> 32);
    return r;
}

__device__ __forceinline__ void mma_tf32(float d[4], const unsigned a[4], const unsigned b[2]) {
    asm volatile(
        "mma.sync.aligned.m16n8k8.row.col.f32.tf32.tf32.f32 "
        "{%0,%1,%2,%3}, {%4,%5,%6,%7}, {%8,%9}, {%0,%1,%2,%3};\n"
        : "+f"(d[0]), "+f"(d[1]), "+f"(d[2]), "+f"(d[3])
        : "r"(a[0]), "r"(a[1]), "r"(a[2]), "r"(a[3]), "r"(b[0]), "r"(b[1]));
}

// ---------------------------------------------------------------------------
// init: g_h[0] = tf32(h0); reset arrival flags.
// ---------------------------------------------------------------------------
__global__ void init_kernel(const float* __restrict__ h0) {
    int i = blockIdx.x * 256 + threadIdx.x;
    if (i < BH) g_h[0][i] = f2tf32(h0[i]);
    if (blockIdx.x == 0 && threadIdx.x < GRID) g_arrive[threadIdx.x] = 0;
}

// ---------------------------------------------------------------------------
// xi = x @ Wi^T + bi.  M=65536, K=512, N=4096. 64x64 block tile, 8 warps.
// ---------------------------------------------------------------------------
__global__ __launch_bounds__(256) void xi_gemm(const float* __restrict__ x,
                                               const float* __restrict__ Wi,
                                               const float* __restrict__ bi) {
    __shared__ __align__(16) unsigned As[64][36];
    __shared__ __align__(16) unsigned Bs[64][36];
    const int n0 = blockIdx.x * 64;
    const int m0 = blockIdx.y * 64;
    const int tid = threadIdx.x;
    const int lane = tid & 31, wid = tid >> 5;
    const int wm = wid >> 2, wn = wid & 3;
    const int g = lane >> 2, tg = lane & 3;

    float acc[2][2][4] = {};

    for (int k0 = 0; k0 < DD; k0 += 32) {
#pragma unroll
        for (int i = 0; i < 2; i++) {
            int f = tid + i * 256;
            int r = f >> 3, kq = (f & 7) << 2;
            float4 v = *(const float4*)(x + (size_t)(m0 + r) * DD + k0 + kq);
            As[r][kq + 0] = f2tf32(v.x); As[r][kq + 1] = f2tf32(v.y);
            As[r][kq + 2] = f2tf32(v.z); As[r][kq + 3] = f2tf32(v.w);
            float4 w = *(const float4*)(Wi + (size_t)(n0 + r) * DD + k0 + kq);
            Bs[r][kq + 0] = f2tf32(w.x); Bs[r][kq + 1] = f2tf32(w.y);
            Bs[r][kq + 2] = f2tf32(w.z); Bs[r][kq + 3] = f2tf32(w.w);
        }
        __syncthreads();

#pragma unroll
        for (int kk = 0; kk < 32; kk += 8) {
            unsigned a[2][4], b[2][2];
#pragma unroll
            for (int mi = 0; mi < 2; mi++) {
                int r = wm * 32 + mi * 16;
                a[mi][0] = As[r + g][kk + tg];
                a[mi][1] = As[r + g + 8][kk + tg];
                a[mi][2] = As[r + g][kk + tg + 4];
                a[mi][3] = As[r + g + 8][kk + tg + 4];
            }
#pragma unroll
            for (int ni = 0; ni < 2; ni++) {
                int c = wn * 16 + ni * 8;
                b[ni][0] = Bs[c + g][kk + tg];
                b[ni][1] = Bs[c + g][kk + tg + 4];
            }
#pragma unroll
            for (int mi = 0; mi < 2; mi++)
#pragma unroll
                for (int ni = 0; ni < 2; ni++)
                    mma_tf32(acc[mi][ni], a[mi], b[ni]);
        }
        __syncthreads();
    }

#pragma unroll
    for (int mi = 0; mi < 2; mi++)
#pragma unroll
        for (int ni = 0; ni < 2; ni++) {
            int row = m0 + wm * 32 + mi * 16 + g;
            int col = n0 + wn * 16 + ni * 8 + 2 * tg;
            float2 bv = *(const float2*)(bi + col);
            *(float2*)(g_xi + (size_t)row * GG + col) =
                make_float2(acc[mi][ni][0] + bv.x, acc[mi][ni][1] + bv.y);
            *(float2*)(g_xi + (size_t)(row + 8) * GG + col) =
                make_float2(acc[mi][ni][2] + bv.x, acc[mi][ni][3] + bv.y);
        }
}

// ---------------------------------------------------------------------------
// Persistent recurrence. grid=128, 256 thr, 1 CTA/SM, all co-resident.
// Block owns 8 hidden columns (32 gate-remapped N cols). Wh tile cached in
// smem as tf32 for the whole kernel. c in registers. Software grid barrier
// per step via per-block flag slots.
// Implicit k-slot permutation: mma slot tg <-> actual k 2*tg, slot tg+4 <->
// 2*tg+1, applied consistently to A (LDG.64 from row-major g_h) and B
// (LDS.64 from k-major Bs) -> dot product unchanged.
// ---------------------------------------------------------------------------
__global__ __launch_bounds__(256, 1) void lstm_persist(
    const float* __restrict__ Wh, const float* __restrict__ bh,
    const int* __restrict__ tok, const float* __restrict__ c0,
    float* __restrict__ out, int ne)
{
    extern __shared__ __align__(16) unsigned Bs[];  // 32 * BSTR words (131.6 KB)
    __shared__ float Ps[64][34];

    const int bid = blockIdx.x;
    const int jb = bid * 8;
    const int tid = threadIdx.x, lane = tid & 31, wid = tid >> 5;
    const int wm = wid >> 1, wn = wid & 1;          // 4 m-warps x 2 n-warps
    const int g = lane >> 2, tg = lane & 3;

    // One-time: Wh gate-remapped rows -> smem tf32. Row n = gate*8 + j.
#pragma unroll
    for (int i = 0; i < 32; i++) {
        int f4 = tid + i * 256;                     // 8192 float4s
        int n = f4 >> 8, q = f4 & 255;
        int grow = (n >> 3) * HH + jb + (n & 7);
        float4 w = *(const float4*)(Wh + (size_t)grow * HH + q * 4);
        unsigned* d = Bs + n * BSTR + q * 4;
        d[0] = f2tf32(w.x); d[1] = f2tf32(w.y);
        d[2] = f2tf32(w.z); d[3] = f2tf32(w.w);
    }

    // Per-thread gate-phase state: outputs (b, j) for o = tid and tid+256.
    const int b_[2] = { tid >> 3, (tid + 256) >> 3 };
    const int j_[2] = { tid & 7, (tid + 256) & 7 };
    float bhv[2][4], creg[2], hreg[2] = {0.f, 0.f};
#pragma unroll
    for (int z = 0; z < 2; z++) {
        int col = jb + j_[z];
#pragma unroll
        for (int gate = 0; gate < 4; gate++) bhv[z][gate] = bh[gate * HH + col];
        creg[z] = c0[(size_t)b_[z] * HH + col];
    }
    __syncthreads();

    for (int t = 0; t < TT; t++) {
        // Prefetch xi for this block's outputs (consumed after the GEMM).
        float xr[2][4];
#pragma unroll
        for (int z = 0; z < 2; z++) {
            const float* xb = g_xi + ((size_t)t * BB + b_[z]) * GG + jb + j_[z];
#pragma unroll
            for (int gate = 0; gate < 4; gate++) xr[z][gate] = __ldcg(xb + gate * HH);
        }

        // GEMM: preact[64 x 32] += h[t-1] @ WhTile^T  (K = 1024).
        const unsigned* gh = g_h[t & 1];
        const unsigned* ar0 = gh + (wm * 16 + g) * HH + 2 * tg;
        const unsigned* ar1 = gh + (wm * 16 + 8 + g) * HH + 2 * tg;
        const unsigned* br0 = Bs + (wn * 16 + g) * BSTR + 2 * tg;
        const unsigned* br1 = Bs + (wn * 16 + 8 + g) * BSTR + 2 * tg;

        float acc[2][2][4] = {};
#pragma unroll 8
        for (int u = 0; u < 128; u++) {
            uint2 a0 = ldcg_u2(ar0 + u * 8);
            uint2 a1 = ldcg_u2(ar1 + u * 8);
            uint2 w0 = *(const uint2*)(br0 + u * 8);
            uint2 w1 = *(const uint2*)(br1 + u * 8);
            unsigned af[4] = { a0.x, a1.x, a0.y, a1.y };
            unsigned b0[2] = { w0.x, w0.y };
            unsigned b1[2] = { w1.x, w1.y };
            mma_tf32(acc[0][u & 1], af, b0);
            mma_tf32(acc[1][u & 1], af, b1);
        }

        // Epilogue -> Ps.
#pragma unroll
        for (int ni = 0; ni < 2; ni++) {
            int c = wn * 16 + ni * 8 + 2 * tg;
            int r = wm * 16 + g;
            Ps[r][c]       = acc[ni][0][0] + acc[ni][1][0];
            Ps[r][c + 1]   = acc[ni][0][1] + acc[ni][1][1];
            Ps[r + 8][c]   = acc[ni][0][2] + acc[ni][1][2];
            Ps[r + 8][c + 1] = acc[ni][0][3] + acc[ni][1][3];
        }
        __syncthreads();

        // Gate phase. c-reset uses tok[t-1] (valid when t>=2); next-step h
        // reset (tok[t]) is folded into the g_h write.
        unsigned* ghn = g_h[(t + 1) & 1];
#pragma unroll
        for (int z = 0; z < 2; z++) {
            int b = b_[z], j = j_[z], col = jb + j;
            float kc = (t >= 2 && __ldg(tok + (t - 1) * BB + b) == 0) ? 0.f : 1.f;
            float pi = Ps[b][j]      + xr[z][0] + bhv[z][0];
            float pf = Ps[b][8 + j]  + xr[z][1] + bhv[z][1];
            float po = Ps[b][16 + j] + xr[z][2] + bhv[z][2];
            float pg = Ps[b][24 + j] + xr[z][3] + bhv[z][3];
            float iv = 1.f / (1.f + __expf(-pi));
            float fv = 1.f / (1.f + __expf(-pf));
            float ov = 1.f / (1.f + __expf(-po));
            float gv = tanhf(pg);
            float cn = fv * creg[z] * kc + iv * gv;
            float hn = ov * tanhf(cn);
            creg[z] = cn; hreg[z] = hn;
            out[(size_t)t * BH + (size_t)b * HH + col] = hn;
            float kn = ((t + 1) >= 2 && __ldg(tok + t * BB + b) == 0) ? 0.f : 1.f;
            ghn[b * HH + col] = f2tf32(hn * kn);
        }

        // Grid barrier: per-block flag slots, warp 0 polls all 128.
        __syncthreads();
        if (tid == 0) {
            __threadfence();
            *(volatile int*)&g_arrive[bid] = t + 1;
        }
        if (tid < 32) {
#pragma unroll
            for (int s = 0; s < 4; s++) {
                volatile int* p = &g_arrive[tid + 32 * s];
                while (*p < t + 1) { }
            }
            __threadfence();
        }
        __syncthreads();
    }

    // hT / cT tail from registers.
#pragma unroll
    for (int z = 0; z < 2; z++) {
        int col = jb + j_[z];
        size_t off = (size_t)b_[z] * HH + col;
        if (ne >= 1) out[TBH + off] = hreg[z];
        if (ne >= 2) out[TBH + BH + off] = creg[z];
    }
}

extern "C" void kernel_launch(void* const* d_in, const int* in_sizes, int n_in,
                              void* d_out, int out_size) {
    const float* x  = (const float*)d_in[0];
    const float* h0 = (const float*)d_in[1];
    const float* c0 = (const float*)d_in[2];
    const float* Wi = (const float*)d_in[3];
    const float* bi = (const float*)d_in[4];
    const float* Wh = (const float*)d_in[5];
    const float* bh = (const float*)d_in[6];
    const int* tok  = (const int*)d_in[7];
    float* out = (float*)d_out;

    const int dyn_smem = 32 * BSTR * 4;  // 131,584 B
    cudaFuncSetAttribute(lstm_persist, cudaFuncAttributeMaxDynamicSharedMemorySize, dyn_smem);

    init_kernel<<<(BH + 255) / 256, 256>>>(h0);
    xi_gemm<<<dim3(GG / 64, (TT * BB) / 64), 256>>>(x, Wi, bi);

    long long extra = ((long long)out_size - (long long)TBH) / BH;
    int ne = extra < 0 ? 0 : (extra > 2 ? 2 : (int)extra);

    lstm_persist<<<GRID, 256, dyn_smem>>>(Wh, bh, tok, c0, out, ne);
}

// round 3
// speedup vs baseline: 1.5231x; 1.5231x over previous
#include <cuda_runtime.h>
#include <cstdint>

// AWD-LSTM persistent kernel, v3: fragment-ready operand layouts.
// T=1024, B=64, DIN=512, H=1024.
// Inputs: x[T,B,DIN], h0[B,H], c0[B,H], Wi[4H,DIN], bi[4H], Wh[4H,H], bh[4H],
//         input_tokens[T,B] i32.  Output: [ out(T*B*H) | hT(B*H) | cT(B*H) ].

#define TT 1024
#define BB 64
#define DD 512
#define HH 1024
#define GG 4096
#define GRID 128
#define BH   (BB * HH)
#define TBH  ((size_t)TT * BB * HH)

// g_h fragment layout: [buf][mb(4)][u(128)][128 words]
//   tile (mb,u) = A-rows [16mb,16mb+16) x k [8u,8u+8), canonical m16n8k8-A:
//   element (r,kin): word = lane*4 + frag, lane=(r&7)*4+(kin&3),
//   frag=((kin>>2)<<1)|(r>>3).
__device__ unsigned g_xiDUMMY_pad;  // keep symbols stable
__device__ float    g_xi[(size_t)TT * BB * GG];   // 1.07 GB scratch
__device__ unsigned g_h[2][BB * HH];
__device__ unsigned g_cnt;
__device__ unsigned g_epoch;

__device__ __forceinline__ unsigned f2tf32(float f) {
    unsigned r;
    asm("cvt.rna.tf32.f32 %0, %1;" : "=r"(r) : "f"(f));
    return r;
}

__device__ __forceinline__ void mma_tf32(float d[4], const unsigned a[4], const unsigned b[2]) {
    asm volatile(
        "mma.sync.aligned.m16n8k8.row.col.f32.tf32.tf32.f32 "
        "{%0,%1,%2,%3}, {%4,%5,%6,%7}, {%8,%9}, {%0,%1,%2,%3};\n"
        : "+f"(d[0]), "+f"(d[1]), "+f"(d[2]), "+f"(d[3])
        : "r"(a[0]), "r"(a[1]), "r"(a[2]), "r"(a[3]), "r"(b[0]), "r"(b[1]));
}

// ---------------------------------------------------------------------------
// init: g_h[0] = tf32(h0) in fragment layout; reset barrier state.
// ---------------------------------------------------------------------------
__global__ void init_kernel(const float* __restrict__ h0) {
    int i = blockIdx.x * 256 + threadIdx.x;
    if (i < BH) {
        int b = i >> 10, col = i & 1023;
        int mb = b >> 4, r = b & 15, u = col >> 3, kin = col & 7;
        int lane = (r & 7) * 4 + (kin & 3);
        int frag = ((kin >> 2) << 1) | (r >> 3);
        g_h[0][((mb << 7 | u) << 7) + lane * 4 + frag] = f2tf32(h0[i]);
    }
    if (blockIdx.x == 0 && threadIdx.x == 0) { g_cnt = 0; g_epoch = 0; }
}

// ---------------------------------------------------------------------------
// xi = x @ Wi^T + bi.  M=65536, K=512, N=4096. 64x64 block tile, 8 warps.
// ---------------------------------------------------------------------------
__global__ __launch_bounds__(256) void xi_gemm(const float* __restrict__ x,
                                               const float* __restrict__ Wi,
                                               const float* __restrict__ bi) {
    __shared__ __align__(16) unsigned As[64][36];
    __shared__ __align__(16) unsigned Bs[64][36];
    const int n0 = blockIdx.x * 64;
    const int m0 = blockIdx.y * 64;
    const int tid = threadIdx.x;
    const int lane = tid & 31, wid = tid >> 5;
    const int wm = wid >> 2, wn = wid & 3;
    const int g = lane >> 2, tg = lane & 3;

    float acc[2][2][4] = {};

    for (int k0 = 0; k0 < DD; k0 += 32) {
#pragma unroll
        for (int i = 0; i < 2; i++) {
            int f = tid + i * 256;
            int r = f >> 3, kq = (f & 7) << 2;
            float4 v = *(const float4*)(x + (size_t)(m0 + r) * DD + k0 + kq);
            As[r][kq + 0] = f2tf32(v.x); As[r][kq + 1] = f2tf32(v.y);
            As[r][kq + 2] = f2tf32(v.z); As[r][kq + 3] = f2tf32(v.w);
            float4 w = *(const float4*)(Wi + (size_t)(n0 + r) * DD + k0 + kq);
            Bs[r][kq + 0] = f2tf32(w.x); Bs[r][kq + 1] = f2tf32(w.y);
            Bs[r][kq + 2] = f2tf32(w.z); Bs[r][kq + 3] = f2tf32(w.w);
        }
        __syncthreads();

#pragma unroll
        for (int kk = 0; kk < 32; kk += 8) {
            unsigned a[2][4], b[2][2];
#pragma unroll
            for (int mi = 0; mi < 2; mi++) {
                int r = wm * 32 + mi * 16;
                a[mi][0] = As[r + g][kk + tg];
                a[mi][1] = As[r + g + 8][kk + tg];
                a[mi][2] = As[r + g][kk + tg + 4];
                a[mi][3] = As[r + g + 8][kk + tg + 4];
            }
#pragma unroll
            for (int ni = 0; ni < 2; ni++) {
                int c = wn * 16 + ni * 8;
                b[ni][0] = Bs[c + g][kk + tg];
                b[ni][1] = Bs[c + g][kk + tg + 4];
            }
#pragma unroll
            for (int mi = 0; mi < 2; mi++)
#pragma unroll
                for (int ni = 0; ni < 2; ni++)
                    mma_tf32(acc[mi][ni], a[mi], b[ni]);
        }
        __syncthreads();
    }

#pragma unroll
    for (int mi = 0; mi < 2; mi++)
#pragma unroll
        for (int ni = 0; ni < 2; ni++) {
            int row = m0 + wm * 32 + mi * 16 + g;
            int col = n0 + wn * 16 + ni * 8 + 2 * tg;
            float2 bv = *(const float2*)(bi + col);
            *(float2*)(g_xi + (size_t)row * GG + col) =
                make_float2(acc[mi][ni][0] + bv.x, acc[mi][ni][1] + bv.y);
            *(float2*)(g_xi + (size_t)(row + 8) * GG + col) =
                make_float2(acc[mi][ni][2] + bv.x, acc[mi][ni][3] + bv.y);
        }
}

// ---------------------------------------------------------------------------
// Persistent recurrence. grid=128 x 256thr, 1 CTA/SM, co-resident.
// Block owns 8 hidden cols (32 gate-remapped N). 8 warps = 2 m-halves x
// 4 k-quarters; no n-split -> h read exactly once per block per step.
// A: LDG.128 of fragment-ready g_h tiles (dense 512B per warp-instr).
// B: LDS.128 from fragment-ready smem, conflict-free interleave
//    [u][half][lane][4]. Reduction: Ps (ks0 write, ks2 add) + Ps2 (ks1/ks3).
// ---------------------------------------------------------------------------
__global__ __launch_bounds__(256, 1) void lstm_persist(
    const float* __restrict__ Wh, const float* __restrict__ bh,
    const int* __restrict__ tok, const float* __restrict__ c0,
    float* __restrict__ out, int ne)
{
    extern __shared__ __align__(16) unsigned Bsf[];  // 128u * 256 words = 128 KB
    __shared__ float Ps[64][33];
    __shared__ float Ps2[64][33];

    const int bid = blockIdx.x;
    const int jb = bid * 8;
    const int tid = threadIdx.x, lane = tid & 31, wid = tid >> 5;
    const int ks = wid >> 1, wmh = wid & 1;          // k-quarter, m-half
    const int g = lane >> 2, tg = lane & 3;

    // One-time: Wh -> fragment-ready smem tf32.
    // word idx = u*256 + g2*128 + lane*4 + q; value = Wh_remap[n][k],
    // n = (g2*2 + (q>>1))*8 + (lane>>2), k = u*8 + (lane&3) + (q&1)*4.
#pragma unroll
    for (int i = 0; i < 128; i++) {
        int idx = tid + i * 256;                     // 0..32767
        int u = idx >> 8, w = idx & 255;
        int g2 = w >> 7, rest = w & 127;
        int ln = rest >> 2, q = rest & 3;
        int nt = g2 * 2 + (q >> 1), hb = q & 1;
        int n = nt * 8 + (ln >> 2);
        int grow = (n >> 3) * HH + jb + (n & 7);
        int k = u * 8 + (ln & 3) + hb * 4;
        Bsf[idx] = f2tf32(__ldg(Wh + (size_t)grow * HH + k));
    }

    // Per-thread gate-phase state: outputs (b, j) for o = tid, tid+256.
    const int b_[2] = { tid >> 3, (tid + 256) >> 3 };
    const int j_[2] = { tid & 7, (tid + 256) & 7 };
    float bhv[2][4], creg[2], hreg[2] = {0.f, 0.f};
#pragma unroll
    for (int z = 0; z < 2; z++) {
        int col = jb + j_[z];
#pragma unroll
        for (int gate = 0; gate < 4; gate++) bhv[z][gate] = bh[gate * HH + col];
        creg[z] = c0[(size_t)b_[z] * HH + col];
    }

    // Precompute h-store addresses (u == bid for this block's columns).
    unsigned hoff[2];
#pragma unroll
    for (int z = 0; z < 2; z++) {
        int b = b_[z], kin = j_[z];
        int mb = b >> 4, r = b & 15;
        int ln = (r & 7) * 4 + (kin & 3);
        int frag = ((kin >> 2) << 1) | (r >> 3);
        hoff[z] = ((unsigned)(mb << 7 | bid) << 7) + ln * 4 + frag;
    }
    __syncthreads();

    for (int t = 0; t < TT; t++) {
        // Prefetch xi for this block's outputs.
        float xr[2][4];
#pragma unroll
        for (int z = 0; z < 2; z++) {
            const float* xb = g_xi + ((size_t)t * BB + b_[z]) * GG + jb + j_[z];
#pragma unroll
            for (int gate = 0; gate < 4; gate++) xr[z][gate] = __ldcg(xb + gate * HH);
        }

        // GEMM: preact[64x32] = h[t-1] @ WhTile^T, K = 1024, k-quarter ks.
        const unsigned* gh = g_h[t & 1];
        const uint4* a0p = (const uint4*)(gh + (((2 * wmh + 0) << 7 | (ks << 5)) << 7)) + lane;
        const uint4* a1p = (const uint4*)(gh + (((2 * wmh + 1) << 7 | (ks << 5)) << 7)) + lane;
        const uint4* bpp = (const uint4*)Bsf + (ks << 5) * 64 + lane;

        float acc[2][4][4] = {};
#pragma unroll 4
        for (int u = 0; u < 32; u++) {
            uint4 A0 = __ldcg(a0p + u * 32);
            uint4 A1 = __ldcg(a1p + u * 32);
            uint4 B0 = bpp[u * 64];
            uint4 B1 = bpp[u * 64 + 32];
            unsigned af0[4] = { A0.x, A0.y, A0.z, A0.w };
            unsigned af1[4] = { A1.x, A1.y, A1.z, A1.w };
            unsigned b00[2] = { B0.x, B0.y }, b01[2] = { B0.z, B0.w };
            unsigned b10[2] = { B1.x, B1.y }, b11[2] = { B1.z, B1.w };
            mma_tf32(acc[0][0], af0, b00); mma_tf32(acc[0][1], af0, b01);
            mma_tf32(acc[0][2], af0, b10); mma_tf32(acc[0][3], af0, b11);
            mma_tf32(acc[1][0], af1, b00); mma_tf32(acc[1][1], af1, b01);
            mma_tf32(acc[1][2], af1, b10); mma_tf32(acc[1][3], af1, b11);
        }

        // Reduction: ks0->Ps, ks1->Ps2 (write); ks2->Ps, ks3->Ps2 (add).
        if (ks < 2) {
            float (*P)[33] = (ks == 0) ? Ps : Ps2;
#pragma unroll
            for (int mbi = 0; mbi < 2; mbi++)
#pragma unroll
                for (int nt = 0; nt < 4; nt++) {
                    int r = (2 * wmh + mbi) * 16 + g;
                    int c = nt * 8 + 2 * tg;
                    P[r][c]     = acc[mbi][nt][0];
                    P[r][c + 1] = acc[mbi][nt][1];
                    P[r + 8][c]     = acc[mbi][nt][2];
                    P[r + 8][c + 1] = acc[mbi][nt][3];
                }
        }
        __syncthreads();
        if (ks >= 2) {
            float (*P)[33] = (ks == 2) ? Ps : Ps2;
#pragma unroll
            for (int mbi = 0; mbi < 2; mbi++)
#pragma unroll
                for (int nt = 0; nt < 4; nt++) {
                    int r = (2 * wmh + mbi) * 16 + g;
                    int c = nt * 8 + 2 * tg;
                    P[r][c]     += acc[mbi][nt][0];
                    P[r][c + 1] += acc[mbi][nt][1];
                    P[r + 8][c]     += acc[mbi][nt][2];
                    P[r + 8][c + 1] += acc[mbi][nt][3];
                }
        }
        __syncthreads();

        // Gate phase. c-reset uses tok[t-1] (t>=2); next-step h reset folded
        // into the g_h fragment write (tok[t]).
        unsigned* ghn = g_h[(t + 1) & 1];
#pragma unroll
        for (int z = 0; z < 2; z++) {
            int b = b_[z], j = j_[z], col = jb + j;
            float kc = (t >= 2 && __ldg(tok + (t - 1) * BB + b) == 0) ? 0.f : 1.f;
            float pi = Ps[b][j]      + Ps2[b][j]      + xr[z][0] + bhv[z][0];
            float pf = Ps[b][8 + j]  + Ps2[b][8 + j]  + xr[z][1] + bhv[z][1];
            float po = Ps[b][16 + j] + Ps2[b][16 + j] + xr[z][2] + bhv[z][2];
            float pg = Ps[b][24 + j] + Ps2[b][24 + j] + xr[z][3] + bhv[z][3];
            float iv = 1.f / (1.f + __expf(-pi));
            float fv = 1.f / (1.f + __expf(-pf));
            float ov = 1.f / (1.f + __expf(-po));
            float gv = tanhf(pg);
            float cn = fv * creg[z] * kc + iv * gv;
            float hn = ov * tanhf(cn);
            creg[z] = cn; hreg[z] = hn;
            out[(size_t)t * BH + (size_t)b * HH + col] = hn;
            float kn = ((t + 1) >= 2 && __ldg(tok + t * BB + b) == 0) ? 0.f : 1.f;
            ghn[hoff[z]] = f2tf32(hn * kn);
        }

        // Grid barrier: counter + epoch, single acquiring poller per block.
        __syncthreads();
        if (tid == 0) {
            __threadfence();
            unsigned old = atomicAdd(&g_cnt, 1u);
            if (old == (unsigned)(t + 1) * GRID - 1u)
                atomicExch(&g_epoch, (unsigned)(t + 1));
            unsigned e;
            do {
                asm volatile("ld.global.acquire.gpu.b32 %0, [%1];"
                             : "=r"(e) : "l"(&g_epoch));
            } while (e < (unsigned)(t + 1));
        }
        __syncthreads();
    }

    // hT / cT tail from registers.
#pragma unroll
    for (int z = 0; z < 2; z++) {
        int col = jb + j_[z];
        size_t off = (size_t)b_[z] * HH + col;
        if (ne >= 1) out[TBH + off] = hreg[z];
        if (ne >= 2) out[TBH + BH + off] = creg[z];
    }
}

extern "C" void kernel_launch(void* const* d_in, const int* in_sizes, int n_in,
                              void* d_out, int out_size) {
    const float* x  = (const float*)d_in[0];
    const float* h0 = (const float*)d_in[1];
    const float* c0 = (const float*)d_in[2];
    const float* Wi = (const float*)d_in[3];
    const float* bi = (const float*)d_in[4];
    const float* Wh = (const float*)d_in[5];
    const float* bh = (const float*)d_in[6];
    const int* tok  = (const int*)d_in[7];
    float* out = (float*)d_out;

    const int dyn_smem = 128 * 256 * 4;  // 131072 B
    cudaFuncSetAttribute(lstm_persist, cudaFuncAttributeMaxDynamicSharedMemorySize, dyn_smem);

    init_kernel<<<(BH + 255) / 256, 256>>>(h0);
    xi_gemm<<<dim3(GG / 64, (TT * BB) / 64), 256>>>(x, Wi, bi);

    long long extra = ((long long)out_size - (long long)TBH) / BH;
    int ne = extra < 0 ? 0 : (extra > 2 ? 2 : (int)extra);

    lstm_persist<<<GRID, 256, dyn_smem>>>(Wh, bh, tok, c0, out, ne);
}

// round 5
// speedup vs baseline: 2.3979x; 1.5743x over previous
#include <cuda_runtime.h>
#include <cuda_fp16.h>
#include <cstdint>

// AWD-LSTM persistent kernel v4b: fp16 recurrent GEMM (m16n8k16), fragment-
// ready layouts. T=1024, B=64, DIN=512, H=1024.
// Inputs: x[T,B,DIN], h0[B,H], c0[B,H], Wi[4H,DIN], bi[4H], Wh[4H,H], bh[4H],
//         input_tokens[T,B] i32.  Output: [ out(T*B*H) | hT(B*H) | cT(B*H) ].

#define TT 1024
#define BB 64
#define DD 512
#define HH 1024
#define GG 4096
#define GRID 128
#define BH   (BB * HH)
#define TBH  ((size_t)TT * BB * HH)

// g_h: fp16, A-fragment layout for m16n8k16.
// [buf][mb(4)][u(64)][32 lanes][4 words]; tile (mb,u) = rows [16mb,16mb+16) x
// k [16u,16u+16). Element (r,kin): lane=(r&7)*4+((kin>>1)&3),
// frag=((kin>>3)<<1)|(r>>3), half lo/hi = kin&1.
__device__ float    g_xi[(size_t)TT * BB * GG];   // 1.07 GB scratch
__device__ unsigned g_h[2][4 * 64 * 128];         // 2 x 128 KB
__device__ unsigned g_cnt;
__device__ unsigned g_epoch;

__device__ __forceinline__ unsigned f2tf32(float f) {
    unsigned r;
    asm("cvt.rna.tf32.f32 %0, %1;" : "=r"(r) : "f"(f));
    return r;
}

// Pack two f32 into one f16x2 word: lo half = x, hi half = y.
__device__ __forceinline__ unsigned f2h2(float x, float y) {
    unsigned r;
    asm("cvt.rn.f16x2.f32 %0, %1, %2;" : "=r"(r) : "f"(y), "f"(x));
    return r;
}

__device__ __forceinline__ void mma_tf32(float d[4], const unsigned a[4], const unsigned b[2]) {
    asm volatile(
        "mma.sync.aligned.m16n8k8.row.col.f32.tf32.tf32.f32 "
        "{%0,%1,%2,%3}, {%4,%5,%6,%7}, {%8,%9}, {%0,%1,%2,%3};\n"
        : "+f"(d[0]), "+f"(d[1]), "+f"(d[2]), "+f"(d[3])
        : "r"(a[0]), "r"(a[1]), "r"(a[2]), "r"(a[3]), "r"(b[0]), "r"(b[1]));
}

__device__ __forceinline__ void mma_f16(float d[4], const unsigned a[4], const unsigned b[2]) {
    asm volatile(
        "mma.sync.aligned.m16n8k16.row.col.f32.f16.f16.f32 "
        "{%0,%1,%2,%3}, {%4,%5,%6,%7}, {%8,%9}, {%0,%1,%2,%3};\n"
        : "+f"(d[0]), "+f"(d[1]), "+f"(d[2]), "+f"(d[3])
        : "r"(a[0]), "r"(a[1]), "r"(a[2]), "r"(a[3]), "r"(b[0]), "r"(b[1]));
}

// ---------------------------------------------------------------------------
// init: g_h[0] = fp16(h0) in fragment layout; reset barrier state.
// ---------------------------------------------------------------------------
__global__ void init_kernel(const float* __restrict__ h0) {
    int w = blockIdx.x * 256 + threadIdx.x;        // word index, 32768 total
    if (w < 4 * 64 * 128) {
        int mb = w >> 13, u = (w >> 7) & 63;
        int lane = (w >> 2) & 31, frag = w & 3;
        int r = ((frag & 1) << 3) | (lane >> 2);
        int kin = ((frag >> 1) << 3) | ((lane & 3) << 1);
        int b = mb * 16 + r, col = u * 16 + kin;
        float2 v = *(const float2*)(h0 + (size_t)b * HH + col);
        g_h[0][w] = f2h2(v.x, v.y);
    }
    if (blockIdx.x == 0 && threadIdx.x == 0) { g_cnt = 0; g_epoch = 0; }
}

// ---------------------------------------------------------------------------
// xi = x @ Wi^T + bi (tf32 GEMM). M=65536, K=512, N=4096.
// ---------------------------------------------------------------------------
__global__ __launch_bounds__(256) void xi_gemm(const float* __restrict__ x,
                                               const float* __restrict__ Wi,
                                               const float* __restrict__ bi) {
    __shared__ __align__(16) unsigned As[64][36];
    __shared__ __align__(16) unsigned Bs[64][36];
    const int n0 = blockIdx.x * 64;
    const int m0 = blockIdx.y * 64;
    const int tid = threadIdx.x;
    const int lane = tid & 31, wid = tid >> 5;
    const int wm = wid >> 2, wn = wid & 3;
    const int g = lane >> 2, tg = lane & 3;

    float acc[2][2][4] = {};

    for (int k0 = 0; k0 < DD; k0 += 32) {
#pragma unroll
        for (int i = 0; i < 2; i++) {
            int f = tid + i * 256;
            int r = f >> 3, kq = (f & 7) << 2;
            float4 v = *(const float4*)(x + (size_t)(m0 + r) * DD + k0 + kq);
            As[r][kq + 0] = f2tf32(v.x); As[r][kq + 1] = f2tf32(v.y);
            As[r][kq + 2] = f2tf32(v.z); As[r][kq + 3] = f2tf32(v.w);
            float4 w = *(const float4*)(Wi + (size_t)(n0 + r) * DD + k0 + kq);
            Bs[r][kq + 0] = f2tf32(w.x); Bs[r][kq + 1] = f2tf32(w.y);
            Bs[r][kq + 2] = f2tf32(w.z); Bs[r][kq + 3] = f2tf32(w.w);
        }
        __syncthreads();

#pragma unroll
        for (int kk = 0; kk < 32; kk += 8) {
            unsigned a[2][4], b[2][2];
#pragma unroll
            for (int mi = 0; mi < 2; mi++) {
                int r = wm * 32 + mi * 16;
                a[mi][0] = As[r + g][kk + tg];
                a[mi][1] = As[r + g + 8][kk + tg];
                a[mi][2] = As[r + g][kk + tg + 4];
                a[mi][3] = As[r + g + 8][kk + tg + 4];
            }
#pragma unroll
            for (int ni = 0; ni < 2; ni++) {
                int c = wn * 16 + ni * 8;
                b[ni][0] = Bs[c + g][kk + tg];
                b[ni][1] = Bs[c + g][kk + tg + 4];
            }
#pragma unroll
            for (int mi = 0; mi < 2; mi++)
#pragma unroll
                for (int ni = 0; ni < 2; ni++)
                    mma_tf32(acc[mi][ni], a[mi], b[ni]);
        }
        __syncthreads();
    }

#pragma unroll
    for (int mi = 0; mi < 2; mi++)
#pragma unroll
        for (int ni = 0; ni < 2; ni++) {
            int row = m0 + wm * 32 + mi * 16 + g;
            int col = n0 + wn * 16 + ni * 8 + 2 * tg;
            float2 bv = *(const float2*)(bi + col);
            *(float2*)(g_xi + (size_t)row * GG + col) =
                make_float2(acc[mi][ni][0] + bv.x, acc[mi][ni][1] + bv.y);
            *(float2*)(g_xi + (size_t)(row + 8) * GG + col) =
                make_float2(acc[mi][ni][2] + bv.x, acc[mi][ni][3] + bv.y);
        }
}

// ---------------------------------------------------------------------------
// Persistent recurrence, fp16 GEMM. grid=128 x 256thr, 1 CTA/SM.
// Block owns 8 hidden cols (N=32 gate-remapped). 8 warps = 2 m-halves x
// 4 k-quarters. Per warp per step: 32 LDG.128 (A) + 32 LDS.128 (B) +
// 128 HMMA.16816.
// Wh smem fragment layout: [u(64)][ntp(2)][lane(32)][4 words]:
//   words = {b0,b1 of nt=2ntp} , {b0,b1 of nt=2ntp+1};
//   b0 = (k=2tg,2tg+1; n=g), b1 = (k=2tg+8,2tg+9; n=g), k global = 16u + kk.
// ---------------------------------------------------------------------------
__global__ __launch_bounds__(256, 1) void lstm_persist(
    const float* __restrict__ Wh, const float* __restrict__ bh,
    const int* __restrict__ tok, const float* __restrict__ c0,
    float* __restrict__ out, int ne)
{
    extern __shared__ __align__(16) unsigned Bsf[];  // 16384 words = 64 KB
    __shared__ float Ps[64][34];
    __shared__ float Ps2[64][34];

    const int bid = blockIdx.x;
    const int jb = bid * 8;
    const int tid = threadIdx.x, lane = tid & 31, wid = tid >> 5;
    const int ks = wid >> 1, wmh = wid & 1;          // k-quarter, m-half
    const int g = lane >> 2, tg = lane & 3;

    // One-time: Wh -> fp16 fragment-ready smem.
#pragma unroll
    for (int i = 0; i < 64; i++) {
        int idx = tid + i * 256;                     // 0..16383
        int u = idx >> 8, rest = idx & 255;
        int ntp = rest >> 7, rr = rest & 127;
        int ln = rr >> 2, w = rr & 3;
        int nt = ntp * 2 + (w >> 1), breg = w & 1;
        int gg = ln >> 2, tt = ln & 3;
        int k = u * 16 + 2 * tt + 8 * breg;
        const float* src = Wh + ((size_t)nt * HH + jb + gg) * HH + k;
        float2 v = *(const float2*)src;
        Bsf[idx] = f2h2(v.x, v.y);
    }

    // Gate-phase mapping: thread -> (b, q), handles j = 2q, 2q+1.
    const int b = tid >> 2, q = tid & 3;
    const int colE = jb + 2 * q;                     // even column
    float2 bhv[4];
#pragma unroll
    for (int gate = 0; gate < 4; gate++)
        bhv[gate] = *(const float2*)(bh + gate * HH + colE);
    float2 creg = *(const float2*)(c0 + (size_t)b * HH + colE);
    float2 hreg = make_float2(0.f, 0.f);

    // h-store word offset in g_h fragment layout (u = bid>>1 fixed).
    unsigned hoff;
    {
        int mb = b >> 4, r = b & 15;
        int kin = 8 * (bid & 1) + 2 * q;
        int ln = (r & 7) * 4 + ((kin >> 1) & 3);
        int frag = ((kin >> 3) << 1) | (r >> 3);
        hoff = ((unsigned)(mb << 6 | (bid >> 1)) << 7) + ln * 4 + frag;
    }
    __syncthreads();

    for (int t = 0; t < TT; t++) {
        // Prefetch xi (consumed after GEMM).
        float2 xr[4];
        {
            const float* xb = g_xi + ((size_t)t * BB + b) * GG + colE;
#pragma unroll
            for (int gate = 0; gate < 4; gate++)
                xr[gate] = *(const float2*)(xb + gate * HH);
        }

        // GEMM: preact[64x32] = h[t-1] @ WhTile^T, K=1024, quarter ks.
        const unsigned* gh = g_h[t & 1];
        const uint4* a0p = (const uint4*)gh + ((2 * wmh + 0) * 64 + ks * 16) * 32 + lane;
        const uint4* a1p = (const uint4*)gh + ((2 * wmh + 1) * 64 + ks * 16) * 32 + lane;
        const uint4* bpp = (const uint4*)Bsf + (ks * 16) * 64 + lane;

        float acc[2][4][4] = {};
#pragma unroll 4
        for (int uu = 0; uu < 16; uu++) {
            uint4 A0 = __ldcg(a0p + uu * 32);
            uint4 A1 = __ldcg(a1p + uu * 32);
            uint4 B0 = bpp[uu * 64];
            uint4 B1 = bpp[uu * 64 + 32];
            unsigned af0[4] = { A0.x, A0.y, A0.z, A0.w };
            unsigned af1[4] = { A1.x, A1.y, A1.z, A1.w };
            unsigned b0[2] = { B0.x, B0.y }, b1[2] = { B0.z, B0.w };
            unsigned b2[2] = { B1.x, B1.y }, b3[2] = { B1.z, B1.w };
            mma_f16(acc[0][0], af0, b0); mma_f16(acc[0][1], af0, b1);
            mma_f16(acc[0][2], af0, b2); mma_f16(acc[0][3], af0, b3);
            mma_f16(acc[1][0], af1, b0); mma_f16(acc[1][1], af1, b1);
            mma_f16(acc[1][2], af1, b2); mma_f16(acc[1][3], af1, b3);
        }

        // Reduction: ks0->Ps, ks1->Ps2 (write); ks2->Ps, ks3->Ps2 (add).
        if (ks < 2) {
            float (*P)[34] = (ks == 0) ? Ps : Ps2;
#pragma unroll
            for (int mbi = 0; mbi < 2; mbi++)
#pragma unroll
                for (int nt = 0; nt < 4; nt++) {
                    int r = (2 * wmh + mbi) * 16 + g;
                    int c = nt * 8 + 2 * tg;
                    P[r][c]     = acc[mbi][nt][0];
                    P[r][c + 1] = acc[mbi][nt][1];
                    P[r + 8][c]     = acc[mbi][nt][2];
                    P[r + 8][c + 1] = acc[mbi][nt][3];
                }
        }
        __syncthreads();
        if (ks >= 2) {
            float (*P)[34] = (ks == 2) ? Ps : Ps2;
#pragma unroll
            for (int mbi = 0; mbi < 2; mbi++)
#pragma unroll
                for (int nt = 0; nt < 4; nt++) {
                    int r = (2 * wmh + mbi) * 16 + g;
                    int c = nt * 8 + 2 * tg;
                    P[r][c]     += acc[mbi][nt][0];
                    P[r][c + 1] += acc[mbi][nt][1];
                    P[r + 8][c]     += acc[mbi][nt][2];
                    P[r + 8][c + 1] += acc[mbi][nt][3];
                }
        }
        __syncthreads();

        // Gate phase: 2 outputs (b, colE), (b, colE+1).
        {
            float kc = (t >= 2 && __ldg(tok + (t - 1) * BB + b) == 0) ? 0.f : 1.f;
            float pre[4][2];
#pragma unroll
            for (int gate = 0; gate < 4; gate++) {
                int c = gate * 8 + 2 * q;
                pre[gate][0] = Ps[b][c]     + Ps2[b][c]     + xr[gate].x + bhv[gate].x;
                pre[gate][1] = Ps[b][c + 1] + Ps2[b][c + 1] + xr[gate].y + bhv[gate].y;
            }
            float h2[2], c2[2];
#pragma unroll
            for (int z = 0; z < 2; z++) {
                float iv = 1.f / (1.f + __expf(-pre[0][z]));
                float fv = 1.f / (1.f + __expf(-pre[1][z]));
                float ov = 1.f / (1.f + __expf(-pre[2][z]));
                float gv = tanhf(pre[3][z]);
                float cold = (z == 0 ? creg.x : creg.y) * kc;
                float cn = fv * cold + iv * gv;
                c2[z] = cn;
                h2[z] = ov * tanhf(cn);
            }
            creg = make_float2(c2[0], c2[1]);
            hreg = make_float2(h2[0], h2[1]);
            *(float2*)(out + (size_t)t * BH + (size_t)b * HH + colE) = hreg;
            float kn = ((t + 1) >= 2 && __ldg(tok + t * BB + b) == 0) ? 0.f : 1.f;
            g_h[(t + 1) & 1][hoff] = f2h2(h2[0] * kn, h2[1] * kn);
        }

        // Grid barrier: counter + epoch; relaxed poll + trailing fence.
        __syncthreads();
        if (tid == 0) {
            __threadfence();
            unsigned old = atomicAdd(&g_cnt, 1u);
            if (old == (unsigned)(t + 1) * GRID - 1u) {
                __threadfence();
                atomicExch(&g_epoch, (unsigned)(t + 1));
            }
            unsigned e;
            do {
                asm volatile("ld.global.relaxed.gpu.b32 %0, [%1];"
                             : "=r"(e) : "l"(&g_epoch));
            } while (e < (unsigned)(t + 1));
            __threadfence();
        }
        __syncthreads();
    }

    // hT / cT tail from registers.
    {
        size_t off = (size_t)b * HH + colE;
        if (ne >= 1) *(float2*)(out + TBH + off) = hreg;
        if (ne >= 2) *(float2*)(out + TBH + BH + off) = creg;
    }
}

extern "C" void kernel_launch(void* const* d_in, const int* in_sizes, int n_in,
                              void* d_out, int out_size) {
    const float* x  = (const float*)d_in[0];
    const float* h0 = (const float*)d_in[1];
    const float* c0 = (const float*)d_in[2];
    const float* Wi = (const float*)d_in[3];
    const float* bi = (const float*)d_in[4];
    const float* Wh = (const float*)d_in[5];
    const float* bh = (const float*)d_in[6];
    const int* tok  = (const int*)d_in[7];
    float* out = (float*)d_out;

    const int dyn_smem = 16384 * 4;  // 64 KB
    cudaFuncSetAttribute(lstm_persist, cudaFuncAttributeMaxDynamicSharedMemorySize, dyn_smem);

    init_kernel<<<(4 * 64 * 128 + 255) / 256, 256>>>(h0);
    xi_gemm<<<dim3(GG / 64, (TT * BB) / 64), 256>>>(x, Wi, bi);

    long long extra = ((long long)out_size - (long long)TBH) / BH;
    int ne = extra < 0 ? 0 : (extra > 2 ? 2 : (int)extra);

    lstm_persist<<<GRID, 256, dyn_smem>>>(Wh, bh, tok, c0, out, ne);
}